// round 11
// baseline (speedup 1.0000x reference)
#include <cuda_runtime.h>
#include <cstdint>
#include <math.h>

#define Bb 4
#define Ss 1024
#define Dd 1024
#define Ee 8
#define DEe 128
#define SCALEF 0.03125f

// ---------------- scratch ----------------
__device__ float g_scores[(size_t)Ee * Bb * Ss * Ss];   // exp(score*scale), fp32
__device__ float g_psum[(size_t)Ee * Bb * 8 * Ss];      // per (pair, t-tile) row sums
__device__ float g_attn[(size_t)Bb * Ss * Ss];          // tf32-rounded normalized probs
__device__ float g_vt[(size_t)Bb * 2 * DEe * Ss];       // tf32-rounded transposed V [b][se][d][t]

__device__ __forceinline__ uint32_t f2tf(float x) {
    uint32_t u;
    asm("cvt.rna.tf32.f32 %0, %1;" : "=r"(u) : "f"(x));
    return u;
}

__device__ __forceinline__ void mma_tf32(float* d, const uint32_t* a, const uint32_t* b) {
    asm volatile(
        "mma.sync.aligned.m16n8k8.row.col.f32.tf32.tf32.f32 "
        "{%0,%1,%2,%3}, {%4,%5,%6,%7}, {%8,%9}, {%0,%1,%2,%3};"
        : "+f"(d[0]), "+f"(d[1]), "+f"(d[2]), "+f"(d[3])
        : "r"(a[0]), "r"(a[1]), "r"(a[2]), "r"(a[3]), "r"(b[0]), "r"(b[1]));
}

__device__ __forceinline__ void cp16(uint32_t* sdst, const float* gsrc) {
    uint32_t sa = (uint32_t)__cvta_generic_to_shared(sdst);
    asm volatile("cp.async.cg.shared.global [%0], [%1], 16;" :: "r"(sa), "l"(gsrc));
}
#define CP_COMMIT() asm volatile("cp.async.commit_group;" ::: "memory")
#define CP_WAIT2()  asm volatile("cp.async.wait_group 2;" ::: "memory")

// ====================== Kernel 1: QK^T, cp.async 3-stage, fused exp + psum ======================
#define QCH 32
#define QSTR 36
#define QSTAGE (2 * 128 * QSTR)            // u32 per stage (A tile + B tile)
#define QK_SMEM (3 * QSTAGE * 4 + 512)     // 3 stages + ps[128]

__device__ __forceinline__ void qk_issue(const float* Ag, const float* Bg, int kc,
                                         uint32_t* stage, int tid) {
    uint32_t* As = stage;
    uint32_t* Bs = stage + 128 * QSTR;
    int row = tid >> 3, col = (tid & 7) << 2;
#pragma unroll
    for (int i = 0; i < 4; i++) {
        int r = row + 32 * i;
        cp16(&As[r * QSTR + col], Ag + (size_t)r * Dd + kc * QCH + col);
        cp16(&Bs[r * QSTR + col], Bg + (size_t)r * Dd + kc * QCH + col);
    }
}

__global__ void __launch_bounds__(256) qk_mma(const float* __restrict__ Q,
                                              const float* __restrict__ K,
                                              const int* __restrict__ emask) {
    int pair = blockIdx.z;              // e*4 + b
    if (emask[pair] == 0) return;
    int e = pair >> 2, b = pair & 3;
    int t0 = blockIdx.x << 7;
    int s0 = blockIdx.y << 7;

    extern __shared__ uint32_t sh[];
    uint32_t* stg[3] = { sh, sh + QSTAGE, sh + 2 * QSTAGE };
    float* ps = (float*)(sh + 3 * QSTAGE);

    int tid = threadIdx.x;
    int wid = tid >> 5, lane = tid & 31;
    int wm = wid & 1, wn = wid >> 1;    // warps: 2 (m) x 4 (n)
    int gq = lane >> 2, c = lane & 3;

    if (tid < 128) ps[tid] = 0.f;

    const float* Ag = Q + (size_t)(b * Ss + s0) * Dd + e * DEe;
    const float* Bg = K + (size_t)(b * Ss + t0) * Dd + e * DEe;

    float acc[4][4][4] = {};

    qk_issue(Ag, Bg, 0, stg[0], tid); CP_COMMIT();
    qk_issue(Ag, Bg, 1, stg[1], tid); CP_COMMIT();

#pragma unroll 1
    for (int kc = 0; kc < 4; kc++) {
        if (kc + 2 < 4) qk_issue(Ag, Bg, kc + 2, stg[(kc + 2) % 3], tid);
        CP_COMMIT();                    // real or empty group: keeps pending count fixed
        CP_WAIT2();
        __syncthreads();
        const uint32_t* As = stg[kc % 3];
        const uint32_t* Bs = As + 128 * QSTR;
#pragma unroll
        for (int ks = 0; ks < 4; ks++) {
            int k0 = ks * 8;
            uint32_t af[4][4], bf[4][2];
#pragma unroll
            for (int mt = 0; mt < 4; mt++) {
                int r0 = wm * 64 + mt * 16;
                af[mt][0] = As[(r0 + gq) * QSTR + k0 + c];
                af[mt][1] = As[(r0 + gq + 8) * QSTR + k0 + c];
                af[mt][2] = As[(r0 + gq) * QSTR + k0 + c + 4];
                af[mt][3] = As[(r0 + gq + 8) * QSTR + k0 + c + 4];
            }
#pragma unroll
            for (int nt = 0; nt < 4; nt++) {
                int n0 = wn * 32 + nt * 8;
                bf[nt][0] = Bs[(n0 + gq) * QSTR + k0 + c];
                bf[nt][1] = Bs[(n0 + gq) * QSTR + k0 + c + 4];
            }
#pragma unroll
            for (int mt = 0; mt < 4; mt++)
#pragma unroll
                for (int nt = 0; nt < 4; nt++)
                    mma_tf32(acc[mt][nt], af[mt], bf[nt]);
        }
        __syncthreads();
    }

    // Epilogue: exp (fp32) -> store + fp32 row-sum partials
    float* outbase = g_scores + (size_t)pair * Ss * Ss;
#pragma unroll
    for (int mt = 0; mt < 4; mt++) {
        int rl = wm * 64 + mt * 16 + gq;
        float slo = 0.f, shi = 0.f;
#pragma unroll
        for (int nt = 0; nt < 4; nt++) {
            int colg = t0 + wn * 32 + nt * 8 + 2 * c;
            float e0 = __expf(acc[mt][nt][0] * SCALEF);
            float e1 = __expf(acc[mt][nt][1] * SCALEF);
            float e2 = __expf(acc[mt][nt][2] * SCALEF);
            float e3 = __expf(acc[mt][nt][3] * SCALEF);
            *(float2*)(outbase + (size_t)(s0 + rl) * Ss + colg)     = make_float2(e0, e1);
            *(float2*)(outbase + (size_t)(s0 + rl + 8) * Ss + colg) = make_float2(e2, e3);
            slo += e0 + e1; shi += e2 + e3;
        }
        slo += __shfl_xor_sync(0xFFFFFFFF, slo, 1);
        slo += __shfl_xor_sync(0xFFFFFFFF, slo, 2);
        shi += __shfl_xor_sync(0xFFFFFFFF, shi, 1);
        shi += __shfl_xor_sync(0xFFFFFFFF, shi, 2);
        if (c == 0) {
            atomicAdd(&ps[rl], slo);
            atomicAdd(&ps[rl + 8], shi);
        }
    }
    __syncthreads();
    if (tid < 128)
        g_psum[((size_t)pair * 8 + blockIdx.x) * Ss + s0 + tid] = ps[tid];
}

// ====================== Kernel 2: combine — batched psum, 2 streams/thread ======================
__global__ void __launch_bounds__(128) combine_kernel(const int* __restrict__ emask) {
    int row = blockIdx.x;
    int b = row >> 10, s = row & 1023;
    int tid = threadIdx.x;              // 0..127

    // Phase 1: all psum loads batched (high MLP); mscale[e] = routed ? 1/rowsum : 0
    float mscale[Ee];
#pragma unroll
    for (int e = 0; e < Ee; e++) {
        int pair = e * Bb + b;
        int r = emask[pair];
        float sm = 0.f;
#pragma unroll
        for (int nt = 0; nt < 8; nt++)
            sm += g_psum[((size_t)pair * 8 + nt) * Ss + s];
        mscale[e] = r ? (1.0f / sm) : 0.0f;
    }

    // Phase 2: two independent float4 streams per thread
    float4 a0 = make_float4(0.f, 0.f, 0.f, 0.f);
    float4 a1 = make_float4(0.f, 0.f, 0.f, 0.f);
#pragma unroll
    for (int e = 0; e < Ee; e++) {
        float m = mscale[e];
        if (m == 0.f) continue;
        const float* xr = g_scores + ((size_t)(e * Bb + b) * Ss + s) * Ss;
        float4 x0 = *(const float4*)(xr + tid * 4);
        float4 x1 = *(const float4*)(xr + (tid + 128) * 4);
        a0.x += x0.x * m; a0.y += x0.y * m; a0.z += x0.z * m; a0.w += x0.w * m;
        a1.x += x1.x * m; a1.y += x1.y * m; a1.z += x1.z * m; a1.w += x1.w * m;
    }
    uint4 o0, o1;
    o0.x = f2tf(a0.x); o0.y = f2tf(a0.y); o0.z = f2tf(a0.z); o0.w = f2tf(a0.w);
    o1.x = f2tf(a1.x); o1.y = f2tf(a1.y); o1.z = f2tf(a1.z); o1.w = f2tf(a1.w);
    *(uint4*)(g_attn + (size_t)row * Ss + tid * 4)         = o0;
    *(uint4*)(g_attn + (size_t)row * Ss + (tid + 128) * 4) = o1;
}

// ---------------- top-2 (ties -> lower index) ----------------
__device__ __forceinline__ void top2(const float* __restrict__ rp, int b, int& bi, int& si) {
    float best = -1e30f, second = -1e30f;
    bi = -1; si = -1;
#pragma unroll
    for (int e = 0; e < Ee; e++) {
        float v = rp[b * Ee + e];
        if (v > best)        { second = best; si = bi; best = v; bi = e; }
        else if (v > second) { second = v; si = e; }
    }
}

// ====================== Kernel 3: transpose selected V slices (tf32-rounded) ======================
__global__ void __launch_bounds__(256) vt_prep(const float* __restrict__ V,
                                               const float* __restrict__ rp) {
    int tt = blockIdx.x;
    int se = blockIdx.y;
    int b  = blockIdx.z;
    int bi, si; top2(rp, b, bi, si);
    int eSel = (se == 0) ? bi : si;

    __shared__ float tile[64][132];
    int tid = threadIdx.x;
#pragma unroll
    for (int i = 0; i < 8; i++) {
        int v = tid + 256 * i;
        int r = v >> 5;
        int c = (v & 31) << 2;
        float4 val = *(const float4*)(V + ((size_t)(b * Ss + tt * 64 + r)) * Dd + eSel * DEe + c);
        *(float4*)&tile[r][c] = val;
    }
    __syncthreads();
#pragma unroll
    for (int i = 0; i < 8; i++) {
        int v = tid + 256 * i;
        int d = v >> 4;
        int t4 = (v & 15) << 2;
        uint4 o;
        o.x = f2tf(tile[t4][d]);     o.y = f2tf(tile[t4 + 1][d]);
        o.z = f2tf(tile[t4 + 2][d]); o.w = f2tf(tile[t4 + 3][d]);
        *(uint4*)(g_vt + ((size_t)((b * 2 + se) * DEe + d)) * Ss + tt * 64 + t4) = o;
    }
}

// ====================== Kernel 4: out = attn @ V (cp.async 3-stage) + inline zero-fill ======================
#define AK 64
#define ASTR 68
#define STAGE_U32 ((64 + 128) * ASTR)
#define AV_SMEM (3 * STAGE_U32 * 4)

__device__ __forceinline__ void av_issue(const float* Ag, const float* Bg, int kc,
                                         uint32_t* stage, int tid) {
    uint32_t* Abuf = stage;
    uint32_t* Bbuf = stage + 64 * ASTR;
#pragma unroll
    for (int i = 0; i < 4; i++) {       // A: 64 rows x 16 float4
        int idx = tid + 256 * i;
        int row = idx >> 4;
        int col = (idx & 15) << 2;
        cp16(&Abuf[row * ASTR + col], Ag + (size_t)row * Ss + kc * AK + col);
    }
#pragma unroll
    for (int i = 0; i < 8; i++) {       // B: 128 rows x 16 float4
        int idx = tid + 256 * i;
        int row = idx >> 4;
        int col = (idx & 15) << 2;
        cp16(&Bbuf[row * ASTR + col], Bg + (size_t)row * Ss + kc * AK + col);
    }
}

__global__ void __launch_bounds__(256) av_mma(const float* __restrict__ rp,
                                              float* __restrict__ outG) {
    int st = blockIdx.x;                // 0..15 (64 rows each)
    int e  = blockIdx.y;                // 0..7 expert
    int b  = blockIdx.z;
    int tid = threadIdx.x;
    int wid = tid >> 5, lane = tid & 31;
    int s0 = st << 6;

    int bi, si; top2(rp, b, bi, si);
    if (e != bi && e != si) {
        // zero-fill this 64x128 output tile, exit
#pragma unroll
        for (int i = 0; i < 8; i++) {
            int v = tid + 256 * i;
            int r = v >> 5;
            int cc = (v & 31) << 2;
            *(float4*)(outG + ((size_t)(b * Ss + s0 + r)) * Dd + e * DEe + cc) =
                make_float4(0.f, 0.f, 0.f, 0.f);
        }
        return;
    }
    int se = (e == bi) ? 0 : 1;

    extern __shared__ uint32_t sh[];
    uint32_t* stg[3] = { sh, sh + STAGE_U32, sh + 2 * STAGE_U32 };

    int wm = wid & 1, wn = wid >> 1;    // 2 (m) x 4 (n)
    int gq = lane >> 2, c = lane & 3;

    const float* Ag = g_attn + (size_t)(b * Ss + s0) * Ss;
    const float* Bg = g_vt + (size_t)(b * 2 + se) * DEe * Ss;

    float acc[2][4][4] = {};

    av_issue(Ag, Bg, 0, stg[0], tid); CP_COMMIT();
    av_issue(Ag, Bg, 1, stg[1], tid); CP_COMMIT();

#pragma unroll 1
    for (int kc = 0; kc < 16; kc++) {
        if (kc + 2 < 16) av_issue(Ag, Bg, kc + 2, stg[(kc + 2) % 3], tid);
        CP_COMMIT();
        CP_WAIT2();
        __syncthreads();
        const uint32_t* As = stg[kc % 3];
        const uint32_t* Bs = As + 64 * ASTR;
#pragma unroll
        for (int ks = 0; ks < 8; ks++) {
            int k0 = ks * 8;
            uint32_t af[2][4], bf[4][2];
#pragma unroll
            for (int mt = 0; mt < 2; mt++) {
                int r0 = wm * 32 + mt * 16;
                af[mt][0] = As[(r0 + gq) * ASTR + k0 + c];
                af[mt][1] = As[(r0 + gq + 8) * ASTR + k0 + c];
                af[mt][2] = As[(r0 + gq) * ASTR + k0 + c + 4];
                af[mt][3] = As[(r0 + gq + 8) * ASTR + k0 + c + 4];
            }
#pragma unroll
            for (int nt = 0; nt < 4; nt++) {
                int n0 = wn * 32 + nt * 8;
                bf[nt][0] = Bs[(n0 + gq) * ASTR + k0 + c];
                bf[nt][1] = Bs[(n0 + gq) * ASTR + k0 + c + 4];
            }
#pragma unroll
            for (int mt = 0; mt < 2; mt++)
#pragma unroll
                for (int nt = 0; nt < 4; nt++)
                    mma_tf32(acc[mt][nt], af[mt], bf[nt]);
        }
        __syncthreads();
    }

#pragma unroll
    for (int mt = 0; mt < 2; mt++) {
        int rl = wm * 32 + mt * 16 + gq;
#pragma unroll
        for (int nt = 0; nt < 4; nt++) {
            int colg = e * DEe + wn * 32 + nt * 8 + 2 * c;
            *(float2*)(outG + ((size_t)(b * Ss + s0 + rl)) * Dd + colg) =
                make_float2(acc[mt][nt][0], acc[mt][nt][1]);
            *(float2*)(outG + ((size_t)(b * Ss + s0 + rl + 8)) * Dd + colg) =
                make_float2(acc[mt][nt][2], acc[mt][nt][3]);
        }
    }
}

// ---------------- launch ----------------
extern "C" void kernel_launch(void* const* d_in, const int* in_sizes, int n_in,
                              void* d_out, int out_size) {
    const float* Q     = (const float*)d_in[0];
    const float* K     = (const float*)d_in[1];
    const float* V     = (const float*)d_in[2];
    const float* rp    = (const float*)d_in[3];
    const int*   emask = (const int*)  d_in[4];
    float* out = (float*)d_out;

    cudaFuncSetAttribute(qk_mma, cudaFuncAttributeMaxDynamicSharedMemorySize, QK_SMEM);
    cudaFuncSetAttribute(av_mma, cudaFuncAttributeMaxDynamicSharedMemorySize, AV_SMEM);

    vt_prep<<<dim3(16, 2, Bb), 256>>>(V, rp);
    qk_mma<<<dim3(8, 8, Ee * Bb), 256, QK_SMEM>>>(Q, K, emask);
    combine_kernel<<<Bb * Ss, 128>>>(emask);
    av_mma<<<dim3(16, Ee, Bb), 256, AV_SMEM>>>(rp, out);
}

// round 12
// speedup vs baseline: 1.0039x; 1.0039x over previous
#include <cuda_runtime.h>
#include <cstdint>
#include <math.h>

#define Bb 4
#define Ss 1024
#define Dd 1024
#define Ee 8
#define DEe 128
#define SCALEF 0.03125f

// ---------------- scratch ----------------
__device__ float g_scores[(size_t)Ee * Bb * Ss * Ss];   // exp(score*scale), fp32
__device__ float g_psum[(size_t)Ee * Bb * 8 * Ss];      // per (pair, t-tile) row sums
__device__ float g_attn[(size_t)Bb * Ss * Ss];          // tf32-rounded normalized probs
__device__ float g_vt[(size_t)Bb * 2 * DEe * Ss];       // tf32-rounded transposed V [b][se][d][t]

__device__ __forceinline__ uint32_t f2tf(float x) {
    uint32_t u;
    asm("cvt.rna.tf32.f32 %0, %1;" : "=r"(u) : "f"(x));
    return u;
}

__device__ __forceinline__ void mma_tf32(float* d, const uint32_t* a, const uint32_t* b) {
    asm volatile(
        "mma.sync.aligned.m16n8k8.row.col.f32.tf32.tf32.f32 "
        "{%0,%1,%2,%3}, {%4,%5,%6,%7}, {%8,%9}, {%0,%1,%2,%3};"
        : "+f"(d[0]), "+f"(d[1]), "+f"(d[2]), "+f"(d[3])
        : "r"(a[0]), "r"(a[1]), "r"(a[2]), "r"(a[3]), "r"(b[0]), "r"(b[1]));
}

__device__ __forceinline__ void cp16(uint32_t* sdst, const float* gsrc) {
    uint32_t sa = (uint32_t)__cvta_generic_to_shared(sdst);
    asm volatile("cp.async.cg.shared.global [%0], [%1], 16;" :: "r"(sa), "l"(gsrc));
}
#define CP_COMMIT() asm volatile("cp.async.commit_group;" ::: "memory")
#define CP_WAIT2()  asm volatile("cp.async.wait_group 2;" ::: "memory")

// ====================== Kernel 1: QK^T, cp.async 3-stage, fused exp + psum ======================
#define QCH 32
#define QSTR 36
#define QSTAGE (2 * 128 * QSTR)            // u32 per stage (A tile + B tile)
#define QK_SMEM (3 * QSTAGE * 4 + 512)     // 3 stages + ps[128]

__device__ __forceinline__ void qk_issue(const float* Ag, const float* Bg, int kc,
                                         uint32_t* stage, int tid) {
    uint32_t* As = stage;
    uint32_t* Bs = stage + 128 * QSTR;
    int row = tid >> 3, col = (tid & 7) << 2;
#pragma unroll
    for (int i = 0; i < 4; i++) {
        int r = row + 32 * i;
        cp16(&As[r * QSTR + col], Ag + (size_t)r * Dd + kc * QCH + col);
        cp16(&Bs[r * QSTR + col], Bg + (size_t)r * Dd + kc * QCH + col);
    }
}

__global__ void __launch_bounds__(256) qk_mma(const float* __restrict__ Q,
                                              const float* __restrict__ K,
                                              const int* __restrict__ emask) {
    int pair = blockIdx.z;              // e*4 + b
    if (emask[pair] == 0) return;
    int e = pair >> 2, b = pair & 3;
    int t0 = blockIdx.x << 7;
    int s0 = blockIdx.y << 7;

    extern __shared__ uint32_t sh[];
    uint32_t* stg[3] = { sh, sh + QSTAGE, sh + 2 * QSTAGE };
    float* ps = (float*)(sh + 3 * QSTAGE);

    int tid = threadIdx.x;
    int wid = tid >> 5, lane = tid & 31;
    int wm = wid & 1, wn = wid >> 1;    // warps: 2 (m) x 4 (n)
    int gq = lane >> 2, c = lane & 3;

    if (tid < 128) ps[tid] = 0.f;

    const float* Ag = Q + (size_t)(b * Ss + s0) * Dd + e * DEe;
    const float* Bg = K + (size_t)(b * Ss + t0) * Dd + e * DEe;

    float acc[4][4][4] = {};

    qk_issue(Ag, Bg, 0, stg[0], tid); CP_COMMIT();
    qk_issue(Ag, Bg, 1, stg[1], tid); CP_COMMIT();

#pragma unroll 1
    for (int kc = 0; kc < 4; kc++) {
        if (kc + 2 < 4) qk_issue(Ag, Bg, kc + 2, stg[(kc + 2) % 3], tid);
        CP_COMMIT();                    // real or empty group: keeps pending count fixed
        CP_WAIT2();
        __syncthreads();
        const uint32_t* As = stg[kc % 3];
        const uint32_t* Bs = As + 128 * QSTR;
#pragma unroll
        for (int ks = 0; ks < 4; ks++) {
            int k0 = ks * 8;
            uint32_t af[4][4], bf[4][2];
#pragma unroll
            for (int mt = 0; mt < 4; mt++) {
                int r0 = wm * 64 + mt * 16;
                af[mt][0] = As[(r0 + gq) * QSTR + k0 + c];
                af[mt][1] = As[(r0 + gq + 8) * QSTR + k0 + c];
                af[mt][2] = As[(r0 + gq) * QSTR + k0 + c + 4];
                af[mt][3] = As[(r0 + gq + 8) * QSTR + k0 + c + 4];
            }
#pragma unroll
            for (int nt = 0; nt < 4; nt++) {
                int n0 = wn * 32 + nt * 8;
                bf[nt][0] = Bs[(n0 + gq) * QSTR + k0 + c];
                bf[nt][1] = Bs[(n0 + gq) * QSTR + k0 + c + 4];
            }
#pragma unroll
            for (int mt = 0; mt < 4; mt++)
#pragma unroll
                for (int nt = 0; nt < 4; nt++)
                    mma_tf32(acc[mt][nt], af[mt], bf[nt]);
        }
        __syncthreads();
    }

    // Epilogue: exp (fp32) -> store + fp32 row-sum partials
    float* outbase = g_scores + (size_t)pair * Ss * Ss;
#pragma unroll
    for (int mt = 0; mt < 4; mt++) {
        int rl = wm * 64 + mt * 16 + gq;
        float slo = 0.f, shi = 0.f;
#pragma unroll
        for (int nt = 0; nt < 4; nt++) {
            int colg = t0 + wn * 32 + nt * 8 + 2 * c;
            float e0 = __expf(acc[mt][nt][0] * SCALEF);
            float e1 = __expf(acc[mt][nt][1] * SCALEF);
            float e2 = __expf(acc[mt][nt][2] * SCALEF);
            float e3 = __expf(acc[mt][nt][3] * SCALEF);
            *(float2*)(outbase + (size_t)(s0 + rl) * Ss + colg)     = make_float2(e0, e1);
            *(float2*)(outbase + (size_t)(s0 + rl + 8) * Ss + colg) = make_float2(e2, e3);
            slo += e0 + e1; shi += e2 + e3;
        }
        slo += __shfl_xor_sync(0xFFFFFFFF, slo, 1);
        slo += __shfl_xor_sync(0xFFFFFFFF, slo, 2);
        shi += __shfl_xor_sync(0xFFFFFFFF, shi, 1);
        shi += __shfl_xor_sync(0xFFFFFFFF, shi, 2);
        if (c == 0) {
            atomicAdd(&ps[rl], slo);
            atomicAdd(&ps[rl + 8], shi);
        }
    }
    __syncthreads();
    if (tid < 128)
        g_psum[((size_t)pair * 8 + blockIdx.x) * Ss + s0 + tid] = ps[tid];
}

// ====================== Kernel 2: combine (float4, 256 thr, tf32-rounded out) ======================
__global__ void __launch_bounds__(256) combine_kernel(const int* __restrict__ emask) {
    int row = blockIdx.x;
    int b = row >> 10, s = row & 1023;
    int tid = threadIdx.x;

    float4 a = make_float4(0.f, 0.f, 0.f, 0.f);
    for (int e = 0; e < Ee; e++) {
        int pair = e * Bb + b;
        if (emask[pair] == 0) continue;
        float sm = 0.f;
#pragma unroll
        for (int nt = 0; nt < 8; nt++)
            sm += g_psum[((size_t)pair * 8 + nt) * Ss + s];
        float inv = 1.0f / sm;
        float4 x = *(const float4*)(g_scores + ((size_t)pair * Ss + s) * Ss + tid * 4);
        a.x += x.x * inv; a.y += x.y * inv; a.z += x.z * inv; a.w += x.w * inv;
    }
    uint4 o;
    o.x = f2tf(a.x); o.y = f2tf(a.y); o.z = f2tf(a.z); o.w = f2tf(a.w);
    *(uint4*)(g_attn + (size_t)row * Ss + tid * 4) = o;
}

// ---------------- top-2 (ties -> lower index) ----------------
__device__ __forceinline__ void top2(const float* __restrict__ rp, int b, int& bi, int& si) {
    float best = -1e30f, second = -1e30f;
    bi = -1; si = -1;
#pragma unroll
    for (int e = 0; e < Ee; e++) {
        float v = rp[b * Ee + e];
        if (v > best)        { second = best; si = bi; best = v; bi = e; }
        else if (v > second) { second = v; si = e; }
    }
}

// ====================== Kernel 3: transpose selected V slices (tf32-rounded) ======================
__global__ void __launch_bounds__(256) vt_prep(const float* __restrict__ V,
                                               const float* __restrict__ rp) {
    int tt = blockIdx.x;
    int se = blockIdx.y;
    int b  = blockIdx.z;
    int bi, si; top2(rp, b, bi, si);
    int eSel = (se == 0) ? bi : si;

    __shared__ float tile[64][132];
    int tid = threadIdx.x;
#pragma unroll
    for (int i = 0; i < 8; i++) {
        int v = tid + 256 * i;
        int r = v >> 5;
        int c = (v & 31) << 2;
        float4 val = *(const float4*)(V + ((size_t)(b * Ss + tt * 64 + r)) * Dd + eSel * DEe + c);
        *(float4*)&tile[r][c] = val;
    }
    __syncthreads();
#pragma unroll
    for (int i = 0; i < 8; i++) {
        int v = tid + 256 * i;
        int d = v >> 4;
        int t4 = (v & 15) << 2;
        uint4 o;
        o.x = f2tf(tile[t4][d]);     o.y = f2tf(tile[t4 + 1][d]);
        o.z = f2tf(tile[t4 + 2][d]); o.w = f2tf(tile[t4 + 3][d]);
        *(uint4*)(g_vt + ((size_t)((b * 2 + se) * DEe + d)) * Ss + tt * 64 + t4) = o;
    }
}

// ====================== Kernel 4a: zero non-selected expert slices ======================
__global__ void __launch_bounds__(256) zero_out(const float* __restrict__ rp,
                                                float* __restrict__ outG) {
    int e  = blockIdx.x;
    int st = blockIdx.y;                // 32 tiles of 32 rows
    int b  = blockIdx.z;
    int bi, si; top2(rp, b, bi, si);
    if (e == bi || e == si) return;
    int s0 = st << 5;
    int tid = threadIdx.x;
#pragma unroll
    for (int i = 0; i < 4; i++) {
        int v = tid + 256 * i;
        int r = v >> 5;
        int cc = (v & 31) << 2;
        *(float4*)(outG + ((size_t)(b * Ss + s0 + r)) * Dd + e * DEe + cc) =
            make_float4(0.f, 0.f, 0.f, 0.f);
    }
}

// ====================== Kernel 4b: out = attn @ V (cp.async 3-stage, 512 thr) ======================
#define AK 64
#define ASTR 68
#define STAGE_U32 ((64 + 128) * ASTR)
#define AV_SMEM (3 * STAGE_U32 * 4)

__device__ __forceinline__ void av_issue(const float* Ag, const float* Bg, int kc,
                                         uint32_t* stage, int tid) {
    uint32_t* Abuf = stage;
    uint32_t* Bbuf = stage + 64 * ASTR;
#pragma unroll
    for (int i = 0; i < 2; i++) {       // A: 64 rows x 16 float4 = 1024 slots
        int idx = tid + 512 * i;
        int row = idx >> 4;
        int col = (idx & 15) << 2;
        cp16(&Abuf[row * ASTR + col], Ag + (size_t)row * Ss + kc * AK + col);
    }
#pragma unroll
    for (int i = 0; i < 4; i++) {       // B: 128 rows x 16 float4 = 2048 slots
        int idx = tid + 512 * i;
        int row = idx >> 4;
        int col = (idx & 15) << 2;
        cp16(&Bbuf[row * ASTR + col], Bg + (size_t)row * Ss + kc * AK + col);
    }
}

__global__ void __launch_bounds__(512) av_mma(const float* __restrict__ rp,
                                              float* __restrict__ outG) {
    int st = blockIdx.x;                // 0..15 (64 rows each)
    int se = blockIdx.y;                // 0..1 selected expert
    int b  = blockIdx.z;
    int tid = threadIdx.x;
    int wid = tid >> 5, lane = tid & 31;
    int s0 = st << 6;

    int bi, si; top2(rp, b, bi, si);
    int e = (se == 0) ? bi : si;

    extern __shared__ uint32_t sh[];
    uint32_t* stg[3] = { sh, sh + STAGE_U32, sh + 2 * STAGE_U32 };

    int wm = wid & 3, wn = wid >> 2;    // 16 warps: 4 (m, 16 rows) x 4 (n, 32 cols)
    int gq = lane >> 2, c = lane & 3;

    const float* Ag = g_attn + (size_t)(b * Ss + s0) * Ss;
    const float* Bg = g_vt + (size_t)(b * 2 + se) * DEe * Ss;

    float acc[4][4] = {};

    av_issue(Ag, Bg, 0, stg[0], tid); CP_COMMIT();
    av_issue(Ag, Bg, 1, stg[1], tid); CP_COMMIT();

#pragma unroll 1
    for (int kc = 0; kc < 16; kc++) {
        if (kc + 2 < 16) av_issue(Ag, Bg, kc + 2, stg[(kc + 2) % 3], tid);
        CP_COMMIT();
        CP_WAIT2();
        __syncthreads();
        const uint32_t* As = stg[kc % 3];
        const uint32_t* Bs = As + 64 * ASTR;
#pragma unroll
        for (int ks = 0; ks < 8; ks++) {
            int k0 = ks * 8;
            uint32_t af[4], bf[4][2];
            int r0 = wm * 16;
            af[0] = As[(r0 + gq) * ASTR + k0 + c];
            af[1] = As[(r0 + gq + 8) * ASTR + k0 + c];
            af[2] = As[(r0 + gq) * ASTR + k0 + c + 4];
            af[3] = As[(r0 + gq + 8) * ASTR + k0 + c + 4];
#pragma unroll
            for (int nt = 0; nt < 4; nt++) {
                int n0 = wn * 32 + nt * 8;
                bf[nt][0] = Bs[(n0 + gq) * ASTR + k0 + c];
                bf[nt][1] = Bs[(n0 + gq) * ASTR + k0 + c + 4];
            }
#pragma unroll
            for (int nt = 0; nt < 4; nt++)
                mma_tf32(acc[nt], af, bf[nt]);
        }
        __syncthreads();
    }

    int rl = wm * 16 + gq;
#pragma unroll
    for (int nt = 0; nt < 4; nt++) {
        int colg = e * DEe + wn * 32 + nt * 8 + 2 * c;
        *(float2*)(outG + ((size_t)(b * Ss + s0 + rl)) * Dd + colg) =
            make_float2(acc[nt][0], acc[nt][1]);
        *(float2*)(outG + ((size_t)(b * Ss + s0 + rl + 8)) * Dd + colg) =
            make_float2(acc[nt][2], acc[nt][3]);
    }
}

// ---------------- launch ----------------
extern "C" void kernel_launch(void* const* d_in, const int* in_sizes, int n_in,
                              void* d_out, int out_size) {
    const float* Q     = (const float*)d_in[0];
    const float* K     = (const float*)d_in[1];
    const float* V     = (const float*)d_in[2];
    const float* rp    = (const float*)d_in[3];
    const int*   emask = (const int*)  d_in[4];
    float* out = (float*)d_out;

    cudaFuncSetAttribute(qk_mma, cudaFuncAttributeMaxDynamicSharedMemorySize, QK_SMEM);
    cudaFuncSetAttribute(av_mma, cudaFuncAttributeMaxDynamicSharedMemorySize, AV_SMEM);

    vt_prep<<<dim3(16, 2, Bb), 256>>>(V, rp);
    qk_mma<<<dim3(8, 8, Ee * Bb), 256, QK_SMEM>>>(Q, K, emask);
    combine_kernel<<<Bb * Ss, 256>>>(emask);
    zero_out<<<dim3(Ee, 32, Bb), 256>>>(rp, out);
    av_mma<<<dim3(16, 2, Bb), 512, AV_SMEM>>>(rp, out);
}

// round 13
// speedup vs baseline: 1.1033x; 1.0990x over previous
#include <cuda_runtime.h>
#include <cuda_fp16.h>
#include <cstdint>
#include <math.h>

#define Bb 4
#define Ss 1024
#define Dd 1024
#define Ee 8
#define DEe 128
#define SCALEF 0.03125f

// ---------------- scratch ----------------
__device__ __half g_scores[(size_t)Ee * Bb * Ss * Ss];  // exp(score*scale), fp16
__device__ float g_psum[(size_t)Ee * Bb * 8 * Ss];      // per (pair, t-tile) row sums (fp32, exact)
__device__ float g_attn[(size_t)Bb * Ss * Ss];          // tf32-rounded normalized probs
__device__ float g_vt[(size_t)Bb * 2 * DEe * Ss];       // tf32-rounded transposed V [b][se][d][t]

__device__ __forceinline__ uint32_t f2tf(float x) {
    uint32_t u;
    asm("cvt.rna.tf32.f32 %0, %1;" : "=r"(u) : "f"(x));
    return u;
}

__device__ __forceinline__ void mma_tf32(float* d, const uint32_t* a, const uint32_t* b) {
    asm volatile(
        "mma.sync.aligned.m16n8k8.row.col.f32.tf32.tf32.f32 "
        "{%0,%1,%2,%3}, {%4,%5,%6,%7}, {%8,%9}, {%0,%1,%2,%3};"
        : "+f"(d[0]), "+f"(d[1]), "+f"(d[2]), "+f"(d[3])
        : "r"(a[0]), "r"(a[1]), "r"(a[2]), "r"(a[3]), "r"(b[0]), "r"(b[1]));
}

__device__ __forceinline__ void cp16(uint32_t* sdst, const float* gsrc) {
    uint32_t sa = (uint32_t)__cvta_generic_to_shared(sdst);
    asm volatile("cp.async.cg.shared.global [%0], [%1], 16;" :: "r"(sa), "l"(gsrc));
}
#define CP_COMMIT() asm volatile("cp.async.commit_group;" ::: "memory")
#define CP_WAIT2()  asm volatile("cp.async.wait_group 2;" ::: "memory")

// ====================== Kernel 1: QK^T, cp.async 3-stage, fused exp + psum ======================
#define QCH 32
#define QSTR 36
#define QSTAGE (2 * 128 * QSTR)            // u32 per stage (A tile + B tile)
#define QK_SMEM (3 * QSTAGE * 4 + 512)     // 3 stages + ps[128]

__device__ __forceinline__ void qk_issue(const float* Ag, const float* Bg, int kc,
                                         uint32_t* stage, int tid) {
    uint32_t* As = stage;
    uint32_t* Bs = stage + 128 * QSTR;
    int row = tid >> 3, col = (tid & 7) << 2;
#pragma unroll
    for (int i = 0; i < 4; i++) {
        int r = row + 32 * i;
        cp16(&As[r * QSTR + col], Ag + (size_t)r * Dd + kc * QCH + col);
        cp16(&Bs[r * QSTR + col], Bg + (size_t)r * Dd + kc * QCH + col);
    }
}

__global__ void __launch_bounds__(256) qk_mma(const float* __restrict__ Q,
                                              const float* __restrict__ K,
                                              const int* __restrict__ emask) {
    int pair = blockIdx.z;              // e*4 + b
    if (emask[pair] == 0) return;
    int e = pair >> 2, b = pair & 3;
    int t0 = blockIdx.x << 7;
    int s0 = blockIdx.y << 7;

    extern __shared__ uint32_t sh[];
    uint32_t* stg[3] = { sh, sh + QSTAGE, sh + 2 * QSTAGE };
    float* ps = (float*)(sh + 3 * QSTAGE);

    int tid = threadIdx.x;
    int wid = tid >> 5, lane = tid & 31;
    int wm = wid & 1, wn = wid >> 1;    // warps: 2 (m) x 4 (n)
    int gq = lane >> 2, c = lane & 3;

    if (tid < 128) ps[tid] = 0.f;

    const float* Ag = Q + (size_t)(b * Ss + s0) * Dd + e * DEe;
    const float* Bg = K + (size_t)(b * Ss + t0) * Dd + e * DEe;

    float acc[4][4][4] = {};

    qk_issue(Ag, Bg, 0, stg[0], tid); CP_COMMIT();
    qk_issue(Ag, Bg, 1, stg[1], tid); CP_COMMIT();

#pragma unroll 1
    for (int kc = 0; kc < 4; kc++) {
        if (kc + 2 < 4) qk_issue(Ag, Bg, kc + 2, stg[(kc + 2) % 3], tid);
        CP_COMMIT();                    // real or empty group: keeps pending count fixed
        CP_WAIT2();
        __syncthreads();
        const uint32_t* As = stg[kc % 3];
        const uint32_t* Bs = As + 128 * QSTR;
#pragma unroll
        for (int ks = 0; ks < 4; ks++) {
            int k0 = ks * 8;
            uint32_t af[4][4], bf[4][2];
#pragma unroll
            for (int mt = 0; mt < 4; mt++) {
                int r0 = wm * 64 + mt * 16;
                af[mt][0] = As[(r0 + gq) * QSTR + k0 + c];
                af[mt][1] = As[(r0 + gq + 8) * QSTR + k0 + c];
                af[mt][2] = As[(r0 + gq) * QSTR + k0 + c + 4];
                af[mt][3] = As[(r0 + gq + 8) * QSTR + k0 + c + 4];
            }
#pragma unroll
            for (int nt = 0; nt < 4; nt++) {
                int n0 = wn * 32 + nt * 8;
                bf[nt][0] = Bs[(n0 + gq) * QSTR + k0 + c];
                bf[nt][1] = Bs[(n0 + gq) * QSTR + k0 + c + 4];
            }
#pragma unroll
            for (int mt = 0; mt < 4; mt++)
#pragma unroll
                for (int nt = 0; nt < 4; nt++)
                    mma_tf32(acc[mt][nt], af[mt], bf[nt]);
        }
        __syncthreads();
    }

    // Epilogue: exp (fp32) -> fp16 store + exact fp32 row-sum partials
    __half* outbase = g_scores + (size_t)pair * Ss * Ss;
#pragma unroll
    for (int mt = 0; mt < 4; mt++) {
        int rl = wm * 64 + mt * 16 + gq;
        float slo = 0.f, shi = 0.f;
#pragma unroll
        for (int nt = 0; nt < 4; nt++) {
            int colg = t0 + wn * 32 + nt * 8 + 2 * c;
            float e0 = __expf(acc[mt][nt][0] * SCALEF);
            float e1 = __expf(acc[mt][nt][1] * SCALEF);
            float e2 = __expf(acc[mt][nt][2] * SCALEF);
            float e3 = __expf(acc[mt][nt][3] * SCALEF);
            *(__half2*)(outbase + (size_t)(s0 + rl) * Ss + colg)     = __floats2half2_rn(e0, e1);
            *(__half2*)(outbase + (size_t)(s0 + rl + 8) * Ss + colg) = __floats2half2_rn(e2, e3);
            slo += e0 + e1; shi += e2 + e3;
        }
        slo += __shfl_xor_sync(0xFFFFFFFF, slo, 1);
        slo += __shfl_xor_sync(0xFFFFFFFF, slo, 2);
        shi += __shfl_xor_sync(0xFFFFFFFF, shi, 1);
        shi += __shfl_xor_sync(0xFFFFFFFF, shi, 2);
        if (c == 0) {
            atomicAdd(&ps[rl], slo);
            atomicAdd(&ps[rl + 8], shi);
        }
    }
    __syncthreads();
    if (tid < 128)
        g_psum[((size_t)pair * 8 + blockIdx.x) * Ss + s0 + tid] = ps[tid];
}

// ---------------- top-2 (ties -> lower index, matches jax top_k) ----------------
__device__ __forceinline__ void top2(const float* __restrict__ rp, int b, int& bi, int& si) {
    float best = -1e30f, second = -1e30f;
    bi = -1; si = -1;
#pragma unroll
    for (int e = 0; e < Ee; e++) {
        float v = rp[b * Ee + e];
        if (v > best)        { second = best; si = bi; best = v; bi = e; }
        else if (v > second) { second = v; si = e; }
    }
}

// ====================== Kernel 2: combine (fp16 in, tf32 fp32 out) + zero-fill out slices ======================
__global__ void __launch_bounds__(256) combine_kernel(const int* __restrict__ emask,
                                                      const float* __restrict__ rp,
                                                      float* __restrict__ outG) {
    int row = blockIdx.x;               // b*1024 + s
    int b = row >> 10, s = row & 1023;
    int tid = threadIdx.x;

    float4 a = make_float4(0.f, 0.f, 0.f, 0.f);
    for (int e = 0; e < Ee; e++) {
        int pair = e * Bb + b;
        if (emask[pair] == 0) continue;
        float sm = 0.f;
#pragma unroll
        for (int nt = 0; nt < 8; nt++)
            sm += g_psum[((size_t)pair * 8 + nt) * Ss + s];
        float inv = 1.0f / sm;
        uint2 raw = *(const uint2*)(g_scores + ((size_t)pair * Ss + s) * Ss + tid * 4);
        float2 f0 = __half22float2(*reinterpret_cast<__half2*>(&raw.x));
        float2 f1 = __half22float2(*reinterpret_cast<__half2*>(&raw.y));
        a.x += f0.x * inv; a.y += f0.y * inv;
        a.z += f1.x * inv; a.w += f1.y * inv;
    }
    uint4 o;
    o.x = f2tf(a.x); o.y = f2tf(a.y); o.z = f2tf(a.z); o.w = f2tf(a.w);
    *(uint4*)(g_attn + (size_t)row * Ss + tid * 4) = o;

    // zero the 6 non-selected 128-wide output slices of this (b, s) row
    int bi, si; top2(rp, b, bi, si);
    // map tid -> (slice index 0..5, float4 within 32)
    if (tid < 192) {
        int sl = tid >> 5;              // 0..5
        int cc = (tid & 31) << 2;       // float offset in slice
        // sl-th expert among those != bi, si
        int e = 0, cnt = 0, eSel = -1;
#pragma unroll
        for (e = 0; e < Ee; e++) {
            if (e == bi || e == si) continue;
            if (cnt == sl) { eSel = e; }
            cnt++;
        }
        *(float4*)(outG + (size_t)row * Dd + eSel * DEe + cc) =
            make_float4(0.f, 0.f, 0.f, 0.f);
    }
}

// ====================== Kernel 3: transpose selected V slices (tf32-rounded) ======================
__global__ void __launch_bounds__(256) vt_prep(const float* __restrict__ V,
                                               const float* __restrict__ rp) {
    int tt = blockIdx.x;
    int se = blockIdx.y;
    int b  = blockIdx.z;
    int bi, si; top2(rp, b, bi, si);
    int eSel = (se == 0) ? bi : si;

    __shared__ float tile[64][132];
    int tid = threadIdx.x;
#pragma unroll
    for (int i = 0; i < 8; i++) {
        int v = tid + 256 * i;
        int r = v >> 5;
        int c = (v & 31) << 2;
        float4 val = *(const float4*)(V + ((size_t)(b * Ss + tt * 64 + r)) * Dd + eSel * DEe + c);
        *(float4*)&tile[r][c] = val;
    }
    __syncthreads();
#pragma unroll
    for (int i = 0; i < 8; i++) {
        int v = tid + 256 * i;
        int d = v >> 4;
        int t4 = (v & 15) << 2;
        uint4 o;
        o.x = f2tf(tile[t4][d]);     o.y = f2tf(tile[t4 + 1][d]);
        o.z = f2tf(tile[t4 + 2][d]); o.w = f2tf(tile[t4 + 3][d]);
        *(uint4*)(g_vt + ((size_t)((b * 2 + se) * DEe + d)) * Ss + tt * 64 + t4) = o;
    }
}

// ====================== Kernel 4: out = attn @ V (cp.async 3-stage, 256 thr — R6 config) ======================
#define AK 64
#define ASTR 68
#define STAGE_U32 ((64 + 128) * ASTR)
#define AV_SMEM (3 * STAGE_U32 * 4)

__device__ __forceinline__ void av_issue(const float* Ag, const float* Bg, int kc,
                                         uint32_t* stage, int tid) {
    uint32_t* Abuf = stage;
    uint32_t* Bbuf = stage + 64 * ASTR;
#pragma unroll
    for (int i = 0; i < 4; i++) {       // A: 64 rows x 16 float4
        int idx = tid + 256 * i;
        int row = idx >> 4;
        int col = (idx & 15) << 2;
        cp16(&Abuf[row * ASTR + col], Ag + (size_t)row * Ss + kc * AK + col);
    }
#pragma unroll
    for (int i = 0; i < 8; i++) {       // B: 128 rows x 16 float4
        int idx = tid + 256 * i;
        int row = idx >> 4;
        int col = (idx & 15) << 2;
        cp16(&Bbuf[row * ASTR + col], Bg + (size_t)row * Ss + kc * AK + col);
    }
}

__global__ void __launch_bounds__(256) av_mma(const float* __restrict__ rp,
                                              float* __restrict__ outG) {
    int st = blockIdx.x;                // 0..15 (64 rows each)
    int se = blockIdx.y;                // 0..1 selected expert
    int b  = blockIdx.z;
    int tid = threadIdx.x;
    int wid = tid >> 5, lane = tid & 31;
    int s0 = st << 6;

    int bi, si; top2(rp, b, bi, si);
    int e = (se == 0) ? bi : si;

    extern __shared__ uint32_t sh[];
    uint32_t* stg[3] = { sh, sh + STAGE_U32, sh + 2 * STAGE_U32 };

    int wm = wid & 1, wn = wid >> 1;    // 2 (m) x 4 (n)
    int gq = lane >> 2, c = lane & 3;

    const float* Ag = g_attn + (size_t)(b * Ss + s0) * Ss;
    const float* Bg = g_vt + (size_t)(b * 2 + se) * DEe * Ss;

    float acc[2][4][4] = {};

    av_issue(Ag, Bg, 0, stg[0], tid); CP_COMMIT();
    av_issue(Ag, Bg, 1, stg[1], tid); CP_COMMIT();

#pragma unroll 1
    for (int kc = 0; kc < 16; kc++) {
        if (kc + 2 < 16) av_issue(Ag, Bg, kc + 2, stg[(kc + 2) % 3], tid);
        CP_COMMIT();
        CP_WAIT2();
        __syncthreads();
        const uint32_t* As = stg[kc % 3];
        const uint32_t* Bs = As + 64 * ASTR;
#pragma unroll
        for (int ks = 0; ks < 8; ks++) {
            int k0 = ks * 8;
            uint32_t af[2][4], bf[4][2];
#pragma unroll
            for (int mt = 0; mt < 2; mt++) {
                int r0 = wm * 32 + mt * 16;
                af[mt][0] = As[(r0 + gq) * ASTR + k0 + c];
                af[mt][1] = As[(r0 + gq + 8) * ASTR + k0 + c];
                af[mt][2] = As[(r0 + gq) * ASTR + k0 + c + 4];
                af[mt][3] = As[(r0 + gq + 8) * ASTR + k0 + c + 4];
            }
#pragma unroll
            for (int nt = 0; nt < 4; nt++) {
                int n0 = wn * 32 + nt * 8;
                bf[nt][0] = Bs[(n0 + gq) * ASTR + k0 + c];
                bf[nt][1] = Bs[(n0 + gq) * ASTR + k0 + c + 4];
            }
#pragma unroll
            for (int mt = 0; mt < 2; mt++)
#pragma unroll
                for (int nt = 0; nt < 4; nt++)
                    mma_tf32(acc[mt][nt], af[mt], bf[nt]);
        }
        __syncthreads();
    }

#pragma unroll
    for (int mt = 0; mt < 2; mt++) {
        int rl = wm * 32 + mt * 16 + gq;
#pragma unroll
        for (int nt = 0; nt < 4; nt++) {
            int colg = e * DEe + wn * 32 + nt * 8 + 2 * c;
            *(float2*)(outG + ((size_t)(b * Ss + s0 + rl)) * Dd + colg) =
                make_float2(acc[mt][nt][0], acc[mt][nt][1]);
            *(float2*)(outG + ((size_t)(b * Ss + s0 + rl + 8)) * Dd + colg) =
                make_float2(acc[mt][nt][2], acc[mt][nt][3]);
        }
    }
}

// ---------------- launch ----------------
extern "C" void kernel_launch(void* const* d_in, const int* in_sizes, int n_in,
                              void* d_out, int out_size) {
    const float* Q     = (const float*)d_in[0];
    const float* K     = (const float*)d_in[1];
    const float* V     = (const float*)d_in[2];
    const float* rp    = (const float*)d_in[3];
    const int*   emask = (const int*)  d_in[4];
    float* out = (float*)d_out;

    cudaFuncSetAttribute(qk_mma, cudaFuncAttributeMaxDynamicSharedMemorySize, QK_SMEM);
    cudaFuncSetAttribute(av_mma, cudaFuncAttributeMaxDynamicSharedMemorySize, AV_SMEM);

    vt_prep<<<dim3(16, 2, Bb), 256>>>(V, rp);
    qk_mma<<<dim3(8, 8, Ee * Bb), 256, QK_SMEM>>>(Q, K, emask);
    combine_kernel<<<Bb * Ss, 256>>>(emask, rp, out);
    av_mma<<<dim3(16, 2, Bb), 256, AV_SMEM>>>(rp, out);
}